// round 11
// baseline (speedup 1.0000x reference)
#include <cuda_runtime.h>

// Smoother: out = max(pred, (moving_sum_501(reflect_pad_T(pred)) + bias) / 501)
// pred: [B=8, T=16384, C=128] fp32, bias: [1] fp32, out: same shape.
//
// R10: L2-traffic reduction via stream co-scheduling.
// R9 analysis: k2 moves ~312 MB through L2 (3 steady reads + init + store per
// output) ~= the LTS ceiling at 28.5us -> L2-BW-bound, not latency-bound.
// The streams of segment s+8 nearly coincide with those of s:
//   mid(s+8)  = lead(s) + 5 rows
//   trail(s+8)= mid(s)  + 6 rows
// So a block's 4 warps handle segments {s, s+8, s+16, s+24}: near-in-time
// loads to the same 128B lines merge in L1tex / hit L1, cutting unique L2
// read streams per block from 12 to ~6.

#define Bn   8
#define Tn   16384
#define C4   32            // 128 channels / 4 per float4
#define Kn   501
#define Pn   250
#define SEG  32
#define NSEG (Tn / SEG)    // 512
#define TILE 32
#define NT   (Tn / TILE)   // 512
#define WPB  4             // warps per block

// tile-sum scratch: 8 * 512 * 32 float4 = 2 MB
__device__ float4 g_TS[Bn * NT * C4];

__device__ __forceinline__ int refl(int k) {
    if (k < 0) k = -k;
    if (k >= Tn) k = 2 * Tn - 2 - k;
    return k;
}

__device__ __forceinline__ void acc4(float4& a, const float4 v) {
    a.x += v.x; a.y += v.y; a.z += v.z; a.w += v.w;
}
__device__ __forceinline__ void sub4(float4& a, const float4 v) {
    a.x -= v.x; a.y -= v.y; a.z -= v.z; a.w -= v.w;
}

// ---------------------------------------------------------------- kernel 1
__global__ void __launch_bounds__(128) tile_sum_kernel(
    const float4* __restrict__ pred)
{
    const int c = threadIdx.x & 31;
    const int w = threadIdx.x >> 5;
    const int j = blockIdx.x * WPB + w;      // tile 0..NT-1
    const int b = blockIdx.y;

    const float4* p = pred + ((size_t)b * Tn + (size_t)j * TILE) * C4 + c;

    float4 a0 = make_float4(0.f, 0.f, 0.f, 0.f);
    float4 a1 = make_float4(0.f, 0.f, 0.f, 0.f);
    float4 a2 = make_float4(0.f, 0.f, 0.f, 0.f);
    float4 a3 = make_float4(0.f, 0.f, 0.f, 0.f);

    #pragma unroll
    for (int base = 0; base < TILE; base += 8) {
        float4 r[8];
        #pragma unroll
        for (int u = 0; u < 8; u++) r[u] = p[(base + u) * C4];
        #pragma unroll
        for (int u = 0; u < 8; u += 4) {
            acc4(a0, r[u + 0]); acc4(a1, r[u + 1]);
            acc4(a2, r[u + 2]); acc4(a3, r[u + 3]);
        }
    }

    float4 s;
    s.x = (a0.x + a1.x) + (a2.x + a3.x);
    s.y = (a0.y + a1.y) + (a2.y + a3.y);
    s.z = (a0.z + a1.z) + (a2.z + a3.z);
    s.w = (a0.w + a1.w) + (a2.w + a3.w);

    g_TS[((size_t)b * NT + j) * C4 + c] = s;
}

// Sum rows [lo, hi) of column p (stride C4) using tile sums ts where possible.
__device__ __forceinline__ void range_sum(
    const float4* __restrict__ p, const float4* __restrict__ ts,
    int lo, int hi, float4& W)
{
    int jlo = (lo + TILE - 1) / TILE;
    int jhi = hi / TILE;
    if (jhi > jlo) {
        for (int r = lo; r < jlo * TILE; r++) acc4(W, p[r * C4]);
        #pragma unroll 4
        for (int j = jlo; j < jhi; j++)       acc4(W, ts[j * C4]);
        for (int r = jhi * TILE; r < hi; r++) acc4(W, p[r * C4]);
    } else {
        for (int r = lo; r < hi; r++) acc4(W, p[r * C4]);
    }
}

// ---------------------------------------------------------------- kernel 2
__global__ void __launch_bounds__(128, 6) smoother_kernel(
    const float4* __restrict__ pred,
    const float*  __restrict__ bias,
    float4*       __restrict__ out)
{
    const int c  = threadIdx.x & 31;        // float4 lane
    const int w  = threadIdx.x >> 5;        // warp in block
    // Co-scheduling map: block B = r + 8q handles segments s = r + 8w + 32q
    // (w = 0..3). Warp w+1's mid/trail streams trail warp w's lead/mid
    // streams by 5-6 rows -> L1 reuse / miss-merge.
    const int Bb = blockIdx.x;
    const int r_ = Bb & 7;
    const int q_ = Bb >> 3;
    const int s  = r_ + 8 * w + 32 * q_;    // segment 0..NSEG-1
    const int b  = blockIdx.y;
    const int t0 = s * SEG;

    const float4* p  = pred + (size_t)b * Tn * C4 + c;
    float4*       o  = out  + (size_t)b * Tn * C4 + c;
    const float4* ts = g_TS + (size_t)b * NT * C4 + c;

    const float bv  = bias[0];
    const float inv = 1.0f / (float)Kn;

    float4 W;

    // Fast path: tiles s-8..s+7 valid AND steady footprint in-bounds.
    const bool fast = (s >= 8) && (t0 + SEG + Pn + 1 <= Tn);

    if (fast) {
        // ---- init: sum(tiles s-8..s+7)  [rows t0-256 .. t0+255]
        //            - rows [t0-256, t0-251]  (6 surplus low)
        //            - rows [t0+251, t0+255]  (5 surplus high)
        float4 a0 = make_float4(0.f, 0.f, 0.f, 0.f);
        float4 a1 = make_float4(0.f, 0.f, 0.f, 0.f);
        float4 a2 = make_float4(0.f, 0.f, 0.f, 0.f);
        float4 a3 = make_float4(0.f, 0.f, 0.f, 0.f);
        {
            const float4* tq = ts + (s - 8) * C4;          // 16 tiles
            #pragma unroll
            for (int base = 0; base < 16; base += 8) {
                float4 r[8];
                #pragma unroll
                for (int u = 0; u < 8; u++) r[u] = tq[(base + u) * C4];
                #pragma unroll
                for (int u = 0; u < 8; u += 4) {
                    acc4(a0, r[u + 0]); acc4(a1, r[u + 1]);
                    acc4(a2, r[u + 2]); acc4(a3, r[u + 3]);
                }
            }
            const float4* qlo = p + (t0 - 256) * C4;       // 6 rows
            const float4* qhi = p + (t0 + Pn + 1) * C4;    // 5 rows
            float4 e[11];
            #pragma unroll
            for (int u = 0; u < 6; u++) e[u]     = qlo[u * C4];
            #pragma unroll
            for (int u = 0; u < 5; u++) e[6 + u] = qhi[u * C4];
            #pragma unroll
            for (int u = 0; u < 11; u++) {
                if      ((u & 3) == 0) sub4(a0, e[u]);
                else if ((u & 3) == 1) sub4(a1, e[u]);
                else if ((u & 3) == 2) sub4(a2, e[u]);
                else                   sub4(a3, e[u]);
            }
        }
        W.x = (a0.x + a1.x) + (a2.x + a3.x);
        W.y = (a0.y + a1.y) + (a2.y + a3.y);
        W.z = (a0.z + a1.z) + (a2.z + a3.z);
        W.w = (a0.w + a1.w) + (a2.w + a3.w);

        const float4* lead  = p + (t0 + Pn + 1) * C4;
        const float4* trail = p + (t0 - Pn) * C4;
        const float4* mid   = p + t0 * C4;
        float4*       op    = o + t0 * C4;

        // ---- steady: 8 batches of 4 outputs, 12 loads issued up front ----
        for (int ii = 0; ii < SEG; ii += 4) {
            float4 L[4], Tt[4], M[4];
            #pragma unroll
            for (int j = 0; j < 4; j++) {
                L[j]  = lead [(ii + j) * C4];
                Tt[j] = trail[(ii + j) * C4];
                M[j]  = mid  [(ii + j) * C4];
            }
            #pragma unroll
            for (int j = 0; j < 4; j++) {
                float4 r;
                r.x = fmaxf(M[j].x, (W.x + bv) * inv);
                r.y = fmaxf(M[j].y, (W.y + bv) * inv);
                r.z = fmaxf(M[j].z, (W.z + bv) * inv);
                r.w = fmaxf(M[j].w, (W.w + bv) * inv);
                op[(ii + j) * C4] = r;
                W.x += L[j].x - Tt[j].x;
                W.y += L[j].y - Tt[j].y;
                W.z += L[j].z - Tt[j].z;
                W.w += L[j].w - Tt[j].w;
            }
        }
    } else {
        // ---- boundary path: init via contiguous range sums ----
        W = make_float4(0.f, 0.f, 0.f, 0.f);
        int lo = t0 - Pn, hi = t0 + Pn + 1;
        if (lo < 0)  { range_sum(p, ts, 1, 1 - lo, W);               lo = 0;  }
        if (hi > Tn) { range_sum(p, ts, 2 * Tn - 1 - hi, Tn - 1, W); hi = Tn; }
        range_sum(p, ts, lo, hi, W);

        for (int ii = 0; ii < SEG; ii += 4) {
            float4 L[4], Tt[4], M[4];
            #pragma unroll
            for (int j = 0; j < 4; j++) {
                int t = t0 + ii + j;
                L[j]  = p[refl(t + Pn + 1) * C4];
                Tt[j] = p[refl(t - Pn) * C4];
                M[j]  = p[t * C4];
            }
            #pragma unroll
            for (int j = 0; j < 4; j++) {
                float4 r;
                r.x = fmaxf(M[j].x, (W.x + bv) * inv);
                r.y = fmaxf(M[j].y, (W.y + bv) * inv);
                r.z = fmaxf(M[j].z, (W.z + bv) * inv);
                r.w = fmaxf(M[j].w, (W.w + bv) * inv);
                o[(t0 + ii + j) * C4] = r;
                W.x += L[j].x - Tt[j].x;
                W.y += L[j].y - Tt[j].y;
                W.z += L[j].z - Tt[j].z;
                W.w += L[j].w - Tt[j].w;
            }
        }
    }
}

extern "C" void kernel_launch(void* const* d_in, const int* in_sizes, int n_in,
                              void* d_out, int out_size)
{
    const float4* pred = (const float4*)d_in[0];
    const float*  bias = (const float*)d_in[1];
    float4*       out  = (float4*)d_out;

    (void)in_sizes; (void)n_in; (void)out_size;

    dim3 g1(NT / WPB, Bn);     // 128 x 8 blocks, 4 tiles each
    dim3 g2(NSEG / WPB, Bn);   // 128 x 8 blocks, segments {s, s+8, s+16, s+24}
    dim3 blk(32 * WPB);        // 128 threads
    tile_sum_kernel<<<g1, blk>>>(pred);
    smoother_kernel<<<g2, blk>>>(pred, bias, out);
}